// round 2
// baseline (speedup 1.0000x reference)
#include <cuda_runtime.h>
#include <cstdint>

#define HIDDEN 1024
#define SLOTS 16
#define BSZ 512
#define SEGLEN 256

// ---------------- scratch (device globals; no allocation) ----------------
__device__ float g_q1[SLOTS * HIDDEN];
__device__ float g_q2[SLOTS * HIDDEN];
__device__ float g_w2[HIDDEN * HIDDEN];
__device__ float g_b2[HIDDEN];
__device__ float g_sraw[(size_t)BSZ * SEGLEN * SLOTS];   // [b*256+t][s]
__device__ float g_attn[(size_t)BSZ * SLOTS * SEGLEN];   // [b][s][t]
__device__ float g_y[(size_t)BSZ * SLOTS * HIDDEN];      // [b][s][d]

// ---------------- helpers ----------------
__device__ __forceinline__ float tf32r(float x) {
    uint32_t u;
    asm("cvt.rna.tf32.f32 %0, %1;" : "=r"(u) : "f"(x));
    return __uint_as_float(u);
}
__device__ __forceinline__ uint32_t f2u(float x) { return __float_as_uint(x); }

__device__ __forceinline__ void mma8(float* c, const uint32_t* a, const uint32_t* b) {
    asm volatile(
        "mma.sync.aligned.m16n8k8.row.col.f32.tf32.tf32.f32 "
        "{%0,%1,%2,%3},{%4,%5,%6,%7},{%8,%9},{%0,%1,%2,%3};"
        : "+f"(c[0]), "+f"(c[1]), "+f"(c[2]), "+f"(c[3])
        : "r"(a[0]), "r"(a[1]), "r"(a[2]), "r"(a[3]), "r"(b[0]), "r"(b[1]));
}

// ---------------- generic tf32 GEMM ----------------
// C[m,n] = sum_k A[m,k] * (BT ? B[n,k] : B[k,n])  (+ bias[n] if BIAS)
// A row-major [M,K] (lda=K), C row-major [M,N] (ldc=N).
// All dims assumed divisible by tiles (true for all call sites here).
template <int BM, int BN, int BK, int WM, int WN, bool BT, bool BIAS>
__global__ void __launch_bounds__(WM * WN * 32) gemm_tf32(
    const float* __restrict__ A, const float* __restrict__ B,
    float* __restrict__ C, const float* __restrict__ bias,
    int M, int N, int K, long sA, long sB, long sC)
{
    constexpr int THREADS = WM * WN * 32;
    constexpr int LA = BK + 8;                       // float stride, keeps frag loads conflict-free
    constexpr int A_ELEMS = BM * LA;
    constexpr int B_ELEMS = BT ? BN * LA : BK * (BN + 8);
    __shared__ float As[A_ELEMS];
    __shared__ float Bs[B_ELEMS];

    const int bz = blockIdx.z;
    const float* Ag = A + (long)bz * sA;
    const float* Bg = B + (long)bz * sB;
    float* Cg = C + (long)bz * sC;

    const int tid  = threadIdx.x;
    const int lane = tid & 31;
    const int warp = tid >> 5;
    const int r  = lane >> 2;   // 0..7
    const int cq = lane & 3;    // 0..3
    const int wm = warp / WN, wn = warp % WN;
    constexpr int WTM = BM / WM, WTN = BN / WN;
    constexpr int MI = WTM / 16, NI = WTN / 8;
    const int mW = wm * WTM, nW = wn * WTN;
    const int m0 = blockIdx.y * BM;
    const int n0 = blockIdx.x * BN;

    float acc[MI][NI][4];
    #pragma unroll
    for (int mi = 0; mi < MI; mi++)
        #pragma unroll
        for (int ni = 0; ni < NI; ni++)
            #pragma unroll
            for (int j = 0; j < 4; j++) acc[mi][ni][j] = 0.0f;

    for (int k0 = 0; k0 < K; k0 += BK) {
        // ---- load A tile [BM x BK], row-major in smem, convert to tf32 ----
        for (int idx = tid; idx < BM * BK / 4; idx += THREADS) {
            int row = idx >> 3;          // BK/4 == 8
            int k4  = idx & 7;
            float4 v = *(const float4*)(Ag + (long)(m0 + row) * K + k0 + k4 * 4);
            float4 w = make_float4(tf32r(v.x), tf32r(v.y), tf32r(v.z), tf32r(v.w));
            *(float4*)&As[row * LA + k4 * 4] = w;
        }
        // ---- load B tile ----
        if constexpr (BT) {
            // B [N,K] row-major -> Bs[n][k]
            for (int idx = tid; idx < BN * BK / 4; idx += THREADS) {
                int nrow = idx >> 3;
                int k4   = idx & 7;
                float4 v = *(const float4*)(Bg + (long)(n0 + nrow) * K + k0 + k4 * 4);
                float4 w = make_float4(tf32r(v.x), tf32r(v.y), tf32r(v.z), tf32r(v.w));
                *(float4*)&Bs[nrow * LA + k4 * 4] = w;
            }
        } else {
            // B [K,N] row-major -> Bs[k][n]
            constexpr int BN4 = BN / 4;
            for (int idx = tid; idx < BK * BN4; idx += THREADS) {
                int krow = idx / BN4;
                int n4   = idx % BN4;
                float4 v = *(const float4*)(Bg + (long)(k0 + krow) * N + n0 + n4 * 4);
                float4 w = make_float4(tf32r(v.x), tf32r(v.y), tf32r(v.z), tf32r(v.w));
                *(float4*)&Bs[krow * (BN + 8) + n4 * 4] = w;
            }
        }
        __syncthreads();

        #pragma unroll
        for (int k8 = 0; k8 < BK / 8; k8++) {
            uint32_t af[MI][4], bf[NI][2];
            #pragma unroll
            for (int mi = 0; mi < MI; mi++) {
                int mr = mW + mi * 16 + r;
                af[mi][0] = f2u(As[mr * LA + k8 * 8 + cq]);
                af[mi][1] = f2u(As[(mr + 8) * LA + k8 * 8 + cq]);
                af[mi][2] = f2u(As[mr * LA + k8 * 8 + cq + 4]);
                af[mi][3] = f2u(As[(mr + 8) * LA + k8 * 8 + cq + 4]);
            }
            #pragma unroll
            for (int ni = 0; ni < NI; ni++) {
                int nc = nW + ni * 8 + r;
                if constexpr (BT) {
                    bf[ni][0] = f2u(Bs[nc * LA + k8 * 8 + cq]);
                    bf[ni][1] = f2u(Bs[nc * LA + k8 * 8 + cq + 4]);
                } else {
                    bf[ni][0] = f2u(Bs[(k8 * 8 + cq) * (BN + 8) + nc]);
                    bf[ni][1] = f2u(Bs[(k8 * 8 + cq + 4) * (BN + 8) + nc]);
                }
            }
            #pragma unroll
            for (int mi = 0; mi < MI; mi++)
                #pragma unroll
                for (int ni = 0; ni < NI; ni++)
                    mma8(acc[mi][ni], af[mi], bf[ni]);
        }
        __syncthreads();
    }

    // ---- epilogue ----
    #pragma unroll
    for (int mi = 0; mi < MI; mi++) {
        int row = m0 + mW + mi * 16 + r;
        #pragma unroll
        for (int ni = 0; ni < NI; ni++) {
            int col = n0 + nW + ni * 8 + 2 * cq;
            float2 v0 = make_float2(acc[mi][ni][0], acc[mi][ni][1]);
            float2 v1 = make_float2(acc[mi][ni][2], acc[mi][ni][3]);
            if constexpr (BIAS) {
                float b0 = bias[col], b1 = bias[col + 1];
                v0.x += b0; v0.y += b1; v1.x += b0; v1.y += b1;
            }
            *(float2*)(Cg + (long)row * N + col) = v0;
            *(float2*)(Cg + (long)(row + 8) * N + col) = v1;
        }
    }
}

// ---------------- prep kernels ----------------
// q1[s][e] = dot(LQ[s,:], Wq[e,:]) + bq[e]
__global__ void __launch_bounds__(256) k_q1(const float* __restrict__ LQ,
                                            const float* __restrict__ Wq,
                                            const float* __restrict__ bq) {
    int e = blockIdx.x * 256 + threadIdx.x;
    int s = blockIdx.y;
    const float4* lq = (const float4*)(LQ + (long)s * HIDDEN);
    const float4* wq = (const float4*)(Wq + (long)e * HIDDEN);
    float acc = 0.0f;
    #pragma unroll 4
    for (int i = 0; i < HIDDEN / 4; i++) {
        float4 a = lq[i], b = wq[i];
        acc = fmaf(a.x, b.x, acc); acc = fmaf(a.y, b.y, acc);
        acc = fmaf(a.z, b.z, acc); acc = fmaf(a.w, b.w, acc);
    }
    g_q1[(long)s * HIDDEN + e] = acc + bq[e];
}

// Q2[s][d] = sum_e q1[s][e] * Wk[e][d]
__global__ void __launch_bounds__(256) k_q2(const float* __restrict__ Wk) {
    int d = blockIdx.x * 256 + threadIdx.x;
    int s = blockIdx.y;
    const float* q1r = g_q1 + (long)s * HIDDEN;
    float acc = 0.0f;
    #pragma unroll 8
    for (int e = 0; e < HIDDEN; e++)
        acc = fmaf(q1r[e], Wk[(long)e * HIDDEN + d], acc);
    g_q2[(long)s * HIDDEN + d] = acc;
}

// b2[e] = dot(Wo[e,:], bv) + bo[e]
__global__ void __launch_bounds__(256) k_b2(const float* __restrict__ Wo,
                                            const float* __restrict__ bv,
                                            const float* __restrict__ bo) {
    int e = blockIdx.x * 256 + threadIdx.x;
    const float4* wo = (const float4*)(Wo + (long)e * HIDDEN);
    const float4* bvv = (const float4*)bv;
    float acc = 0.0f;
    #pragma unroll 4
    for (int i = 0; i < HIDDEN / 4; i++) {
        float4 a = wo[i], b = bvv[i];
        acc = fmaf(a.x, b.x, acc); acc = fmaf(a.y, b.y, acc);
        acc = fmaf(a.z, b.z, acc); acc = fmaf(a.w, b.w, acc);
    }
    g_b2[e] = acc + bo[e];
}

// ---------------- softmax over t (exact fp32) ----------------
// in: g_sraw[(b*256+t)*16 + s]; out: g_attn[(b*16+s)*256 + t]
__global__ void __launch_bounds__(256) softmax_k(const float* __restrict__ logits) {
    int b = blockIdx.x, s = blockIdx.y, t = threadIdx.x;
    int lane = t & 31, wid = t >> 5;
    __shared__ float sm[8];

    float v = g_sraw[((long)(b * SEGLEN + t)) * SLOTS + s] * 0.03125f
            + logits[(long)b * SEGLEN + t];

    // block max
    float m = v;
    #pragma unroll
    for (int o = 16; o; o >>= 1) m = fmaxf(m, __shfl_xor_sync(0xffffffffu, m, o));
    if (lane == 0) sm[wid] = m;
    __syncthreads();
    if (t < 8) {
        float x = sm[t];
        #pragma unroll
        for (int o = 4; o; o >>= 1) x = fmaxf(x, __shfl_xor_sync(0xffu, x, o));
        if (t == 0) sm[0] = x;
    }
    __syncthreads();
    m = sm[0];
    float e = expf(v - m);
    __syncthreads();   // done reading sm[0] before reuse

    // block sum
    float sum = e;
    #pragma unroll
    for (int o = 16; o; o >>= 1) sum += __shfl_xor_sync(0xffffffffu, sum, o);
    if (lane == 0) sm[wid] = sum;
    __syncthreads();
    if (t < 8) {
        float x = sm[t];
        #pragma unroll
        for (int o = 4; o; o >>= 1) x += __shfl_xor_sync(0xffu, x, o);
        if (t == 0) sm[0] = x;
    }
    __syncthreads();

    g_attn[((long)b * SLOTS + s) * SEGLEN + t] = e / sm[0];
}

// ---------------- launch ----------------
extern "C" void kernel_launch(void* const* d_in, const int* in_sizes, int n_in,
                              void* d_out, int out_size) {
    const float* X      = (const float*)d_in[0];   // segment_states [512,256,1024]
    const float* logits = (const float*)d_in[1];   // [512,256]
    const float* LQ     = (const float*)d_in[2];   // [16,1024]
    const float* Wq     = (const float*)d_in[3];
    const float* bq     = (const float*)d_in[4];
    const float* Wk     = (const float*)d_in[5];
    // d_in[6] = bk: cancels in softmax, unused
    const float* Wv     = (const float*)d_in[7];
    const float* bv     = (const float*)d_in[8];
    const float* Wo     = (const float*)d_in[9];
    const float* bo     = (const float*)d_in[10];
    float* out = (float*)d_out;

    float *q2p, *w2p, *b2p, *srawp, *attnp, *yp;
    cudaGetSymbolAddress((void**)&q2p,   g_q2);
    cudaGetSymbolAddress((void**)&w2p,   g_w2);
    cudaGetSymbolAddress((void**)&b2p,   g_b2);
    cudaGetSymbolAddress((void**)&srawp, g_sraw);
    cudaGetSymbolAddress((void**)&attnp, g_attn);
    cudaGetSymbolAddress((void**)&yp,    g_y);

    // 1) q1 = LQ @ Wq^T + bq ; Q2 = q1 @ Wk ; b2 = Wo @ bv + bo
    k_q1<<<dim3(4, 16), 256>>>(LQ, Wq, bq);
    k_q2<<<dim3(4, 16), 256>>>(Wk);
    k_b2<<<4, 256>>>(Wo, bv, bo);

    // 2) W2 = Wo @ Wv   [1024,1024] = [1024,1024] @ [1024,1024]  (NN)
    gemm_tf32<128, 64, 32, 2, 4, false, false><<<dim3(16, 8, 1), 256>>>(
        Wo, Wv, w2p, nullptr, 1024, 1024, 1024, 0, 0, 0);

    // 3) raw scores: S[b*256+t][s] = X[b,t,:] . Q2[s,:]   (B transposed)
    gemm_tf32<128, 16, 32, 8, 1, true, false><<<dim3(1, (BSZ * SEGLEN) / 128, 1), 256>>>(
        X, q2p, srawp, nullptr, BSZ * SEGLEN, SLOTS, HIDDEN, 0, 0, 0);

    // 4) softmax over t with scale + importance logits
    softmax_k<<<dim3(BSZ, SLOTS), 256>>>(logits);

    // 5) Y[b] = attn[b] @ X[b]   [16,1024] = [16,256] @ [256,1024]  (NN, batched over b)
    gemm_tf32<16, 64, 32, 1, 8, false, false><<<dim3(16, 1, BSZ), 256>>>(
        attnp, X, yp, nullptr, SLOTS, HIDDEN, SEGLEN,
        (long)SLOTS * SEGLEN, (long)SEGLEN * HIDDEN, (long)SLOTS * HIDDEN);

    // 6) out = Y @ W2^T + b2   [8192,1024] = [8192,1024] @ [1024,1024]^T
    gemm_tf32<128, 64, 32, 2, 4, true, true><<<dim3(16, 64, 1), 256>>>(
        yp, w2p, out, b2p, BSZ * SLOTS, HIDDEN, HIDDEN, 0, 0, 0);
}

// round 4
// speedup vs baseline: 1.4018x; 1.4018x over previous
#include <cuda_runtime.h>
#include <cstdint>

#define HIDDEN 1024
#define SLOTS 16
#define BSZ 512
#define SEGLEN 256
#define TT 16            // t-tile in fused attention
#define SCALE 0.03125f   // 1/sqrt(1024)

// ---------------- scratch (device globals; no allocation) ----------------
__device__ float g_q1[SLOTS * HIDDEN];
__device__ float g_q2[SLOTS * HIDDEN];
__device__ float g_w2[HIDDEN * HIDDEN];
__device__ float g_b2[HIDDEN];
__device__ float g_y[(size_t)BSZ * SLOTS * HIDDEN];      // [b][s][d]

// ---------------- helpers ----------------
__device__ __forceinline__ float tf32r(float x) {
    uint32_t u;
    asm("cvt.rna.tf32.f32 %0, %1;" : "=r"(u) : "f"(x));
    return __uint_as_float(u);
}
__device__ __forceinline__ float4 tf32r4(float4 v) {
    return make_float4(tf32r(v.x), tf32r(v.y), tf32r(v.z), tf32r(v.w));
}
__device__ __forceinline__ uint32_t f2u(float x) { return __float_as_uint(x); }

__device__ __forceinline__ void mma8(float* c, const uint32_t* a, const uint32_t* b) {
    asm volatile(
        "mma.sync.aligned.m16n8k8.row.col.f32.tf32.tf32.f32 "
        "{%0,%1,%2,%3},{%4,%5,%6,%7},{%8,%9},{%0,%1,%2,%3};"
        : "+f"(c[0]), "+f"(c[1]), "+f"(c[2]), "+f"(c[3])
        : "r"(a[0]), "r"(a[1]), "r"(a[2]), "r"(a[3]), "r"(b[0]), "r"(b[1]));
}

__device__ __forceinline__ uint32_t smem_u32(const void* p) {
    uint32_t a;
    asm("{ .reg .u64 t; cvta.to.shared.u64 t, %1; cvt.u32.u64 %0, t; }" : "=r"(a) : "l"(p));
    return a;
}
__device__ __forceinline__ void cpasync16(uint32_t dst, const void* src) {
    asm volatile("cp.async.cg.shared.global [%0], [%1], 16;" :: "r"(dst), "l"(src));
}
#define CP_COMMIT() asm volatile("cp.async.commit_group;")
#define CP_WAIT(n)  asm volatile("cp.async.wait_group %0;" :: "n"(n))

// ---------------- pipelined tf32 GEMM ----------------
// C[m,n] = sum_k A[m,k] * (BT ? B[n,k] : B[k,n])  (+ bias[n] if BIAS)
// Double-buffered smem + register prefetch of next k-tile.
template <int BM, int BN, int BK, int WM, int WN, bool BT, bool BIAS, bool RNA>
__global__ void __launch_bounds__(WM * WN * 32) gemm_p(
    const float* __restrict__ A, const float* __restrict__ B,
    float* __restrict__ C, const float* __restrict__ bias,
    int M, int N, int K)
{
    constexpr int THREADS = WM * WN * 32;
    constexpr int LA = BK + 8;
    constexpr int ASZ = BM * LA;
    constexpr int BSZE = BT ? BN * LA : BK * (BN + 8);
    constexpr int AREG = BM * BK / 4 / THREADS;
    constexpr int BREG = BN * BK / 4 / THREADS;

    extern __shared__ float sm[];
    float* AsB[2] = { sm, sm + ASZ };
    float* BsB[2] = { sm + 2 * ASZ, sm + 2 * ASZ + BSZE };

    const int tid  = threadIdx.x;
    const int lane = tid & 31;
    const int warp = tid >> 5;
    const int r  = lane >> 2;
    const int cq = lane & 3;
    const int wm = warp / WN, wn = warp % WN;
    constexpr int WTM = BM / WM, WTN = BN / WN;
    constexpr int MI = WTM / 16, NI = WTN / 8;
    const int mW = wm * WTM, nW = wn * WTN;
    const int m0 = blockIdx.y * BM;
    const int n0 = blockIdx.x * BN;

    float acc[MI][NI][4];
    #pragma unroll
    for (int mi = 0; mi < MI; mi++)
        #pragma unroll
        for (int ni = 0; ni < NI; ni++)
            #pragma unroll
            for (int j = 0; j < 4; j++) acc[mi][ni][j] = 0.0f;

    float4 ra[AREG], rb[BREG];

    auto ldgA = [&](int k0) {
        #pragma unroll
        for (int i = 0; i < AREG; i++) {
            int idx = i * THREADS + tid;
            int row = idx / (BK / 4), k4 = idx % (BK / 4);
            ra[i] = *(const float4*)(A + (long)(m0 + row) * K + k0 + k4 * 4);
        }
    };
    auto ldgB = [&](int k0) {
        if constexpr (BT) {
            #pragma unroll
            for (int i = 0; i < BREG; i++) {
                int idx = i * THREADS + tid;
                int row = idx / (BK / 4), k4 = idx % (BK / 4);
                rb[i] = *(const float4*)(B + (long)(n0 + row) * K + k0 + k4 * 4);
            }
        } else {
            #pragma unroll
            for (int i = 0; i < BREG; i++) {
                int idx = i * THREADS + tid;
                int row = idx / (BN / 4), n4 = idx % (BN / 4);
                rb[i] = *(const float4*)(B + (long)(k0 + row) * N + n0 + n4 * 4);
            }
        }
    };
    auto sts = [&](int buf) {
        #pragma unroll
        for (int i = 0; i < AREG; i++) {
            int idx = i * THREADS + tid;
            int row = idx / (BK / 4), k4 = idx % (BK / 4);
            *(float4*)&AsB[buf][row * LA + k4 * 4] = tf32r4(ra[i]);
        }
        if constexpr (BT) {
            #pragma unroll
            for (int i = 0; i < BREG; i++) {
                int idx = i * THREADS + tid;
                int row = idx / (BK / 4), k4 = idx % (BK / 4);
                *(float4*)&BsB[buf][row * LA + k4 * 4] = tf32r4(rb[i]);
            }
        } else {
            #pragma unroll
            for (int i = 0; i < BREG; i++) {
                int idx = i * THREADS + tid;
                int row = idx / (BN / 4), n4 = idx % (BN / 4);
                *(float4*)&BsB[buf][row * (BN + 8) + n4 * 4] = tf32r4(rb[i]);
            }
        }
    };
    auto compute = [&](int buf) {
        const float* As = AsB[buf];
        const float* Bs = BsB[buf];
        #pragma unroll
        for (int k8 = 0; k8 < BK / 8; k8++) {
            uint32_t af[MI][4], bf[NI][2];
            #pragma unroll
            for (int mi = 0; mi < MI; mi++) {
                int mr = mW + mi * 16 + r;
                af[mi][0] = f2u(As[mr * LA + k8 * 8 + cq]);
                af[mi][1] = f2u(As[(mr + 8) * LA + k8 * 8 + cq]);
                af[mi][2] = f2u(As[mr * LA + k8 * 8 + cq + 4]);
                af[mi][3] = f2u(As[(mr + 8) * LA + k8 * 8 + cq + 4]);
            }
            #pragma unroll
            for (int ni = 0; ni < NI; ni++) {
                int nc = nW + ni * 8 + r;
                if constexpr (BT) {
                    bf[ni][0] = f2u(Bs[nc * LA + k8 * 8 + cq]);
                    bf[ni][1] = f2u(Bs[nc * LA + k8 * 8 + cq + 4]);
                } else {
                    bf[ni][0] = f2u(Bs[(k8 * 8 + cq) * (BN + 8) + nc]);
                    bf[ni][1] = f2u(Bs[(k8 * 8 + cq + 4) * (BN + 8) + nc]);
                }
            }
            #pragma unroll
            for (int mi = 0; mi < MI; mi++)
                #pragma unroll
                for (int ni = 0; ni < NI; ni++)
                    mma8(acc[mi][ni], af[mi], bf[ni]);
        }
    };

    // pipeline
    ldgA(0); ldgB(0); sts(0); __syncthreads();
    const int NTILES = K / BK;
    for (int t = 0; t < NTILES; t++) {
        int cur = t & 1;
        if (t + 1 < NTILES) { ldgA((t + 1) * BK); ldgB((t + 1) * BK); }
        compute(cur);
        if (t + 1 < NTILES) sts(cur ^ 1);
        __syncthreads();
    }

    // epilogue
    #pragma unroll
    for (int mi = 0; mi < MI; mi++) {
        int row = m0 + mW + mi * 16 + r;
        #pragma unroll
        for (int ni = 0; ni < NI; ni++) {
            int col = n0 + nW + ni * 8 + 2 * cq;
            float2 v0 = make_float2(acc[mi][ni][0], acc[mi][ni][1]);
            float2 v1 = make_float2(acc[mi][ni][2], acc[mi][ni][3]);
            if constexpr (BIAS) {
                float b0 = bias[col], b1 = bias[col + 1];
                v0.x += b0; v0.y += b1; v1.x += b0; v1.y += b1;
            }
            if constexpr (RNA) {
                v0.x = tf32r(v0.x); v0.y = tf32r(v0.y);
                v1.x = tf32r(v1.x); v1.y = tf32r(v1.y);
            }
            *(float2*)(C + (long)row * N + col) = v0;
            *(float2*)(C + (long)(row + 8) * N + col) = v1;
        }
    }
}

// ---------------- b2[e] = dot(Wo[e,:], bv) + bo[e] ----------------
__global__ void __launch_bounds__(256) k_b2(const float* __restrict__ Wo,
                                            const float* __restrict__ bv,
                                            const float* __restrict__ bo) {
    int e = blockIdx.x * 256 + threadIdx.x;
    const float4* wo = (const float4*)(Wo + (long)e * HIDDEN);
    const float4* bvv = (const float4*)bv;
    float acc = 0.0f;
    #pragma unroll 4
    for (int i = 0; i < HIDDEN / 4; i++) {
        float4 a = wo[i], b = bvv[i];
        acc = fmaf(a.x, b.x, acc); acc = fmaf(a.y, b.y, acc);
        acc = fmaf(a.z, b.z, acc); acc = fmaf(a.w, b.w, acc);
    }
    g_b2[e] = acc + bo[e];
}

// ---------------- fused attention: scores + softmax + Y, X read once ----------------
// grid.x = BSZ, 256 threads (8 warps). Each warp owns a 128-wide d-chunk of Y.
#define LQ2 1032
#define OFF_Q2 0
#define OFF_X  (16 * LQ2)
#define OFF_SP (OFF_X + 2 * TT * LQ2)
#define OFF_P  (OFF_SP + 8 * 16 * TT)
#define OFF_M  (OFF_P + 16 * 24)
#define OFF_L  (OFF_M + 16)
#define OFF_SC (OFF_L + 16)
#define OFF_LG (OFF_SC + 16)
#define FUSED_SMEM ((OFF_LG + SEGLEN) * 4)

__global__ void __launch_bounds__(256) fused_attn(
    const float* __restrict__ X, const float* __restrict__ logits,
    float* __restrict__ Y)
{
    extern __shared__ float sm[];
    float* Q2s = sm + OFF_Q2;
    float* Xs  = sm + OFF_X;
    float* Sp  = sm + OFF_SP;
    float* Ps  = sm + OFF_P;
    float* mS  = sm + OFF_M;
    float* lS  = sm + OFF_L;
    float* scS = sm + OFF_SC;
    float* lgS = sm + OFF_LG;

    const int b    = blockIdx.x;
    const int tid  = threadIdx.x;
    const int lane = tid & 31;
    const int w    = tid >> 5;
    const int r    = lane >> 2;
    const int cq   = lane & 3;
    const float* Xb = X + (long)b * SEGLEN * HIDDEN;

    auto issueX = [&](int it) {
        int buf = it & 1;
        const float* src0 = Xb + (long)it * TT * HIDDEN;
        uint32_t dstb = smem_u32(Xs + buf * TT * LQ2);
        #pragma unroll
        for (int i = 0; i < 16; i++) {
            int idx = i * 256 + tid;          // 4096 float4 per stage
            int row = idx >> 8, c4 = idx & 255;
            cpasync16(dstb + (row * LQ2 + c4 * 4) * 4, src0 + row * HIDDEN + c4 * 4);
        }
        CP_COMMIT();
    };
    issueX(0);

    // preload logits + Q2 (Q2 already RNA-rounded)
    lgS[tid] = logits[(long)b * SEGLEN + tid];
    #pragma unroll
    for (int i = 0; i < 16; i++) {
        int idx = i * 256 + tid;
        int row = idx >> 8, c4 = idx & 255;
        *(float4*)&Q2s[row * LQ2 + c4 * 4] = *(const float4*)(g_q2 + row * HIDDEN + c4 * 4);
    }
    if (tid < 16) { mS[tid] = -INFINITY; lS[tid] = 0.0f; }

    float acc[16][4];
    #pragma unroll
    for (int ni = 0; ni < 16; ni++)
        #pragma unroll
        for (int j = 0; j < 4; j++) acc[ni][j] = 0.0f;

    __syncthreads();

    const int NT = SEGLEN / TT;   // 16 tiles
    for (int it = 0; it < NT; it++) {
        int buf = it & 1;
        if (it + 1 < NT) { issueX(it + 1); CP_WAIT(1); } else { CP_WAIT(0); }
        __syncthreads();
        const float* Xt = Xs + buf * TT * LQ2;

        // ---- scores: each warp covers d in [w*128, w*128+128) ----
        {
            float sacc[2][4] = {{0,0,0,0},{0,0,0,0}};
            #pragma unroll
            for (int k8 = 0; k8 < 16; k8++) {
                int kk = w * 128 + k8 * 8;
                uint32_t af[4], bf[2][2];
                af[0] = f2u(Q2s[r * LQ2 + kk + cq]);
                af[1] = f2u(Q2s[(r + 8) * LQ2 + kk + cq]);
                af[2] = f2u(Q2s[r * LQ2 + kk + cq + 4]);
                af[3] = f2u(Q2s[(r + 8) * LQ2 + kk + cq + 4]);
                #pragma unroll
                for (int nt = 0; nt < 2; nt++) {
                    int nc = nt * 8 + r;
                    bf[nt][0] = f2u(Xt[nc * LQ2 + kk + cq]);
                    bf[nt][1] = f2u(Xt[nc * LQ2 + kk + cq + 4]);
                }
                mma8(sacc[0], af, bf[0]);
                mma8(sacc[1], af, bf[1]);
            }
            #pragma unroll
            for (int nt = 0; nt < 2; nt++) {
                int c0 = nt * 8 + 2 * cq;
                Sp[(w * 16 + r) * TT + c0]         = sacc[nt][0];
                Sp[(w * 16 + r) * TT + c0 + 1]     = sacc[nt][1];
                Sp[(w * 16 + r + 8) * TT + c0]     = sacc[nt][2];
                Sp[(w * 16 + r + 8) * TT + c0 + 1] = sacc[nt][3];
            }
        }
        __syncthreads();

        // ---- online softmax, fully parallel: thread (s = tid>>4, t = tid&15) ----
        {
            int s = tid >> 4, t = tid & 15;
            float accs = 0.0f;
            #pragma unroll
            for (int ww = 0; ww < 8; ww++) accs += Sp[(ww * 16 + s) * TT + t];
            float v = accs * SCALE + lgS[it * TT + t];
            float m_t = v;
            #pragma unroll
            for (int o = 8; o; o >>= 1) m_t = fmaxf(m_t, __shfl_xor_sync(0xffffffffu, m_t, o));
            float m_old = mS[s];                  // read by all 16 lanes of the group
            float newm = fmaxf(m_old, m_t);
            float p = expf(v - newm);
            Ps[s * 24 + t] = tf32r(p);
            float sum = p;
            #pragma unroll
            for (int o = 8; o; o >>= 1) sum += __shfl_xor_sync(0xffffffffu, sum, o);
            if (t == 0) {
                float scale = expf(m_old - newm); // 0 on first tile
                lS[s] = lS[s] * scale + sum;
                mS[s] = newm;
                scS[s] = scale;
            }
        }
        __syncthreads();

        // ---- rescale Y acc, then Y += P @ X_tile ----
        {
            float sc0 = scS[r], sc1 = scS[r + 8];
            #pragma unroll
            for (int ni = 0; ni < 16; ni++) {
                acc[ni][0] *= sc0; acc[ni][1] *= sc0;
                acc[ni][2] *= sc1; acc[ni][3] *= sc1;
            }
            #pragma unroll
            for (int k8 = 0; k8 < 2; k8++) {
                uint32_t af[4];
                af[0] = f2u(Ps[r * 24 + k8 * 8 + cq]);
                af[1] = f2u(Ps[(r + 8) * 24 + k8 * 8 + cq]);
                af[2] = f2u(Ps[r * 24 + k8 * 8 + cq + 4]);
                af[3] = f2u(Ps[(r + 8) * 24 + k8 * 8 + cq + 4]);
                #pragma unroll
                for (int ni = 0; ni < 16; ni++) {
                    int nc = w * 128 + ni * 8 + r;
                    uint32_t bf[2];
                    bf[0] = f2u(Xt[(k8 * 8 + cq) * LQ2 + nc]);
                    bf[1] = f2u(Xt[(k8 * 8 + cq + 4) * LQ2 + nc]);
                    mma8(acc[ni], af, bf);
                }
            }
        }
        __syncthreads();   // protect Xs buffer + Ps/scS/mS/lS before next tile
    }

    // ---- epilogue: Y[b][s][d] = acc / l, RNA-rounded ----
    float inv0 = 1.0f / lS[r];
    float inv1 = 1.0f / lS[r + 8];
    float* Y0 = Y + ((long)b * SLOTS + r) * HIDDEN;
    float* Y1 = Y + ((long)b * SLOTS + r + 8) * HIDDEN;
    #pragma unroll
    for (int ni = 0; ni < 16; ni++) {
        int col = w * 128 + ni * 8 + 2 * cq;
        float2 v0 = make_float2(tf32r(acc[ni][0] * inv0), tf32r(acc[ni][1] * inv0));
        float2 v1 = make_float2(tf32r(acc[ni][2] * inv1), tf32r(acc[ni][3] * inv1));
        *(float2*)(Y0 + col) = v0;
        *(float2*)(Y1 + col) = v1;
    }
}

// ---------------- launch ----------------
extern "C" void kernel_launch(void* const* d_in, const int* in_sizes, int n_in,
                              void* d_out, int out_size) {
    const float* X      = (const float*)d_in[0];   // [512,256,1024]
    const float* logits = (const float*)d_in[1];   // [512,256]
    const float* LQ     = (const float*)d_in[2];   // [16,1024]
    const float* Wq     = (const float*)d_in[3];
    const float* bq     = (const float*)d_in[4];
    const float* Wk     = (const float*)d_in[5];
    // d_in[6] = bk: cancels in softmax, unused
    const float* Wv     = (const float*)d_in[7];
    const float* bv     = (const float*)d_in[8];
    const float* Wo     = (const float*)d_in[9];
    const float* bo     = (const float*)d_in[10];
    float* out = (float*)d_out;

    float *q1p, *q2p, *w2p, *b2p, *yp;
    cudaGetSymbolAddress((void**)&q1p, g_q1);
    cudaGetSymbolAddress((void**)&q2p, g_q2);
    cudaGetSymbolAddress((void**)&w2p, g_w2);
    cudaGetSymbolAddress((void**)&b2p, g_b2);
    cudaGetSymbolAddress((void**)&yp,  g_y);

    // opt-in smem for the big kernels (idempotent host calls)
    cudaFuncSetAttribute((const void*)gemm_p<128,128,32,2,4,true,true,false>,
                         cudaFuncAttributeMaxDynamicSharedMemorySize, 81920);
    cudaFuncSetAttribute((const void*)fused_attn,
                         cudaFuncAttributeMaxDynamicSharedMemorySize, FUSED_SMEM);

    // 1) q1 = LQ @ Wq^T + bq    [16,1024]
    gemm_p<16, 64, 32, 1, 4, true, true, true><<<dim3(16, 1), 128, 25600>>>(
        LQ, Wq, q1p, bq, 16, 1024, 1024);
    // 2) Q2 = q1 @ Wk           [16,1024]
    gemm_p<16, 64, 32, 1, 4, false, false, true><<<dim3(16, 1), 128, 23552>>>(
        q1p, Wk, q2p, nullptr, 16, 1024, 1024);
    // 3) b2 = Wo @ bv + bo
    k_b2<<<4, 256>>>(Wo, bv, bo);
    // 4) W2 = Wo @ Wv           [1024,1024]
    gemm_p<64, 64, 32, 2, 2, false, false, true><<<dim3(16, 16), 128, 38912>>>(
        Wo, Wv, w2p, nullptr, 1024, 1024, 1024);
    // 5) fused attention: Y[b] = softmax(Q2·X^T/32 + logits) @ X   (X read once)
    fused_attn<<<BSZ, 256, FUSED_SMEM>>>(X, logits, yp);
    // 6) out = Y @ W2^T + b2    [8192,1024]
    gemm_p<128, 128, 32, 2, 4, true, true, false><<<dim3(8, 64), 256, 81920>>>(
        yp, w2p, out, b2p, BSZ * SLOTS, HIDDEN, HIDDEN);
}

// round 5
// speedup vs baseline: 1.7460x; 1.2456x over previous
#include <cuda_runtime.h>
#include <cstdint>

#define HIDDEN 1024
#define SLOTS 16
#define BSZ 512
#define SEGLEN 256
#define TT 16            // t-tile in fused attention
#define SCALE 0.03125f   // 1/sqrt(1024)

// ---------------- scratch (device globals; no allocation) ----------------
__device__ float g_q1[SLOTS * HIDDEN];
__device__ float g_q2[SLOTS * HIDDEN];
__device__ float g_w2[HIDDEN * HIDDEN];
__device__ float g_b2[HIDDEN];
__device__ float g_y[(size_t)BSZ * SLOTS * HIDDEN];      // [b][s][d]

// ---------------- helpers ----------------
__device__ __forceinline__ float tf32r(float x) {
    uint32_t u;
    asm("cvt.rna.tf32.f32 %0, %1;" : "=r"(u) : "f"(x));
    return __uint_as_float(u);
}
__device__ __forceinline__ float4 tf32r4(float4 v) {
    return make_float4(tf32r(v.x), tf32r(v.y), tf32r(v.z), tf32r(v.w));
}
__device__ __forceinline__ uint32_t f2u(float x) { return __float_as_uint(x); }

__device__ __forceinline__ void mma8(float* c, const uint32_t* a, const uint32_t* b) {
    asm volatile(
        "mma.sync.aligned.m16n8k8.row.col.f32.tf32.tf32.f32 "
        "{%0,%1,%2,%3},{%4,%5,%6,%7},{%8,%9},{%0,%1,%2,%3};"
        : "+f"(c[0]), "+f"(c[1]), "+f"(c[2]), "+f"(c[3])
        : "r"(a[0]), "r"(a[1]), "r"(a[2]), "r"(a[3]), "r"(b[0]), "r"(b[1]));
}

__device__ __forceinline__ uint32_t smem_u32(const void* p) {
    uint32_t a;
    asm("{ .reg .u64 t; cvta.to.shared.u64 t, %1; cvt.u32.u64 %0, t; }" : "=r"(a) : "l"(p));
    return a;
}
__device__ __forceinline__ void cpasync16(uint32_t dst, const void* src) {
    asm volatile("cp.async.cg.shared.global [%0], [%1], 16;" :: "r"(dst), "l"(src));
}
#define CP_COMMIT() asm volatile("cp.async.commit_group;")
#define CP_WAIT(n)  asm volatile("cp.async.wait_group %0;" :: "n"(n))

// ---------------- pipelined tf32 GEMM (LDG+convert path, for raw-fp32 inputs) ----------------
template <int BM, int BN, int BK, int WM, int WN, bool BT, bool BIAS, bool RNA>
__global__ void __launch_bounds__(WM * WN * 32) gemm_p(
    const float* __restrict__ A, const float* __restrict__ B,
    float* __restrict__ C, const float* __restrict__ bias,
    int M, int N, int K)
{
    constexpr int THREADS = WM * WN * 32;
    constexpr int LA = BK + 8;
    constexpr int ASZ = BM * LA;
    constexpr int BSZE = BT ? BN * LA : BK * (BN + 8);
    constexpr int AREG = BM * BK / 4 / THREADS;
    constexpr int BREG = BN * BK / 4 / THREADS;

    extern __shared__ float sm[];
    float* AsB[2] = { sm, sm + ASZ };
    float* BsB[2] = { sm + 2 * ASZ, sm + 2 * ASZ + BSZE };

    const int tid  = threadIdx.x;
    const int lane = tid & 31;
    const int warp = tid >> 5;
    const int r  = lane >> 2;
    const int cq = lane & 3;
    const int wm = warp / WN, wn = warp % WN;
    constexpr int WTM = BM / WM, WTN = BN / WN;
    constexpr int MI = WTM / 16, NI = WTN / 8;
    const int mW = wm * WTM, nW = wn * WTN;
    const int m0 = blockIdx.y * BM;
    const int n0 = blockIdx.x * BN;

    float acc[MI][NI][4];
    #pragma unroll
    for (int mi = 0; mi < MI; mi++)
        #pragma unroll
        for (int ni = 0; ni < NI; ni++)
            #pragma unroll
            for (int j = 0; j < 4; j++) acc[mi][ni][j] = 0.0f;

    float4 ra[AREG], rb[BREG];

    auto ldgA = [&](int k0) {
        #pragma unroll
        for (int i = 0; i < AREG; i++) {
            int idx = i * THREADS + tid;
            int row = idx / (BK / 4), k4 = idx % (BK / 4);
            ra[i] = *(const float4*)(A + (long)(m0 + row) * K + k0 + k4 * 4);
        }
    };
    auto ldgB = [&](int k0) {
        if constexpr (BT) {
            #pragma unroll
            for (int i = 0; i < BREG; i++) {
                int idx = i * THREADS + tid;
                int row = idx / (BK / 4), k4 = idx % (BK / 4);
                rb[i] = *(const float4*)(B + (long)(n0 + row) * K + k0 + k4 * 4);
            }
        } else {
            #pragma unroll
            for (int i = 0; i < BREG; i++) {
                int idx = i * THREADS + tid;
                int row = idx / (BN / 4), n4 = idx % (BN / 4);
                rb[i] = *(const float4*)(B + (long)(k0 + row) * N + n0 + n4 * 4);
            }
        }
    };
    auto sts = [&](int buf) {
        #pragma unroll
        for (int i = 0; i < AREG; i++) {
            int idx = i * THREADS + tid;
            int row = idx / (BK / 4), k4 = idx % (BK / 4);
            *(float4*)&AsB[buf][row * LA + k4 * 4] = tf32r4(ra[i]);
        }
        if constexpr (BT) {
            #pragma unroll
            for (int i = 0; i < BREG; i++) {
                int idx = i * THREADS + tid;
                int row = idx / (BK / 4), k4 = idx % (BK / 4);
                *(float4*)&BsB[buf][row * LA + k4 * 4] = tf32r4(rb[i]);
            }
        } else {
            #pragma unroll
            for (int i = 0; i < BREG; i++) {
                int idx = i * THREADS + tid;
                int row = idx / (BN / 4), n4 = idx % (BN / 4);
                *(float4*)&BsB[buf][row * (BN + 8) + n4 * 4] = tf32r4(rb[i]);
            }
        }
    };
    auto compute = [&](int buf) {
        const float* As = AsB[buf];
        const float* Bs = BsB[buf];
        #pragma unroll
        for (int k8 = 0; k8 < BK / 8; k8++) {
            uint32_t af[MI][4], bf[NI][2];
            #pragma unroll
            for (int mi = 0; mi < MI; mi++) {
                int mr = mW + mi * 16 + r;
                af[mi][0] = f2u(As[mr * LA + k8 * 8 + cq]);
                af[mi][1] = f2u(As[(mr + 8) * LA + k8 * 8 + cq]);
                af[mi][2] = f2u(As[mr * LA + k8 * 8 + cq + 4]);
                af[mi][3] = f2u(As[(mr + 8) * LA + k8 * 8 + cq + 4]);
            }
            #pragma unroll
            for (int ni = 0; ni < NI; ni++) {
                int nc = nW + ni * 8 + r;
                if constexpr (BT) {
                    bf[ni][0] = f2u(Bs[nc * LA + k8 * 8 + cq]);
                    bf[ni][1] = f2u(Bs[nc * LA + k8 * 8 + cq + 4]);
                } else {
                    bf[ni][0] = f2u(Bs[(k8 * 8 + cq) * (BN + 8) + nc]);
                    bf[ni][1] = f2u(Bs[(k8 * 8 + cq + 4) * (BN + 8) + nc]);
                }
            }
            #pragma unroll
            for (int mi = 0; mi < MI; mi++)
                #pragma unroll
                for (int ni = 0; ni < NI; ni++)
                    mma8(acc[mi][ni], af[mi], bf[ni]);
        }
    };

    ldgA(0); ldgB(0); sts(0); __syncthreads();
    const int NTILES = K / BK;
    for (int t = 0; t < NTILES; t++) {
        int cur = t & 1;
        if (t + 1 < NTILES) { ldgA((t + 1) * BK); ldgB((t + 1) * BK); }
        compute(cur);
        if (t + 1 < NTILES) sts(cur ^ 1);
        __syncthreads();
    }

    #pragma unroll
    for (int mi = 0; mi < MI; mi++) {
        int row = m0 + mW + mi * 16 + r;
        #pragma unroll
        for (int ni = 0; ni < NI; ni++) {
            int col = n0 + nW + ni * 8 + 2 * cq;
            float2 v0 = make_float2(acc[mi][ni][0], acc[mi][ni][1]);
            float2 v1 = make_float2(acc[mi][ni][2], acc[mi][ni][3]);
            if constexpr (BIAS) {
                float b0 = bias[col], b1 = bias[col + 1];
                v0.x += b0; v0.y += b1; v1.x += b0; v1.y += b1;
            }
            if constexpr (RNA) {
                v0.x = tf32r(v0.x); v0.y = tf32r(v0.y);
                v1.x = tf32r(v1.x); v1.y = tf32r(v1.y);
            }
            *(float2*)(C + (long)row * N + col) = v0;
            *(float2*)(C + (long)(row + 8) * N + col) = v1;
        }
    }
}

// ---------------- cp.async tf32 GEMM (inputs must already be tf32-exact) ----------------
template <int BM, int BN, int BK, int WM, int WN, bool BIAS>
__global__ void __launch_bounds__(WM * WN * 32, 2) gemm_cpa(
    const float* __restrict__ A, const float* __restrict__ B,   // B is [N,K] (BT)
    float* __restrict__ C, const float* __restrict__ bias,
    int M, int N, int K)
{
    constexpr int THREADS = WM * WN * 32;
    constexpr int LA = BK + 8;
    constexpr int ASZ = BM * LA;
    constexpr int BSZE = BN * LA;
    constexpr int AITER = BM * BK / 4 / THREADS;
    constexpr int BITER = BN * BK / 4 / THREADS;

    extern __shared__ float sm[];
    float* AsB[2] = { sm, sm + ASZ };
    float* BsB[2] = { sm + 2 * ASZ, sm + 2 * ASZ + BSZE };

    const int tid  = threadIdx.x;
    const int lane = tid & 31;
    const int warp = tid >> 5;
    const int r  = lane >> 2;
    const int cq = lane & 3;
    const int wm = warp / WN, wn = warp % WN;
    constexpr int WTM = BM / WM, WTN = BN / WN;
    constexpr int MI = WTM / 16, NI = WTN / 8;
    const int mW = wm * WTM, nW = wn * WTN;
    const int m0 = blockIdx.y * BM;
    const int n0 = blockIdx.x * BN;

    float acc[MI][NI][4];
    #pragma unroll
    for (int mi = 0; mi < MI; mi++)
        #pragma unroll
        for (int ni = 0; ni < NI; ni++)
            #pragma unroll
            for (int j = 0; j < 4; j++) acc[mi][ni][j] = 0.0f;

    auto issue = [&](int k0, int buf) {
        uint32_t ab = smem_u32(AsB[buf]);
        uint32_t bb = smem_u32(BsB[buf]);
        #pragma unroll
        for (int i = 0; i < AITER; i++) {
            int idx = i * THREADS + tid;
            int row = idx / (BK / 4), k4 = idx % (BK / 4);
            cpasync16(ab + (row * LA + k4 * 4) * 4,
                      A + (long)(m0 + row) * K + k0 + k4 * 4);
        }
        #pragma unroll
        for (int i = 0; i < BITER; i++) {
            int idx = i * THREADS + tid;
            int row = idx / (BK / 4), k4 = idx % (BK / 4);
            cpasync16(bb + (row * LA + k4 * 4) * 4,
                      B + (long)(n0 + row) * K + k0 + k4 * 4);
        }
        CP_COMMIT();
    };
    auto compute = [&](int buf) {
        const float* As = AsB[buf];
        const float* Bs = BsB[buf];
        #pragma unroll
        for (int k8 = 0; k8 < BK / 8; k8++) {
            uint32_t af[MI][4], bf[NI][2];
            #pragma unroll
            for (int mi = 0; mi < MI; mi++) {
                int mr = mW + mi * 16 + r;
                af[mi][0] = f2u(As[mr * LA + k8 * 8 + cq]);
                af[mi][1] = f2u(As[(mr + 8) * LA + k8 * 8 + cq]);
                af[mi][2] = f2u(As[mr * LA + k8 * 8 + cq + 4]);
                af[mi][3] = f2u(As[(mr + 8) * LA + k8 * 8 + cq + 4]);
            }
            #pragma unroll
            for (int ni = 0; ni < NI; ni++) {
                int nc = nW + ni * 8 + r;
                bf[ni][0] = f2u(Bs[nc * LA + k8 * 8 + cq]);
                bf[ni][1] = f2u(Bs[nc * LA + k8 * 8 + cq + 4]);
            }
            #pragma unroll
            for (int mi = 0; mi < MI; mi++)
                #pragma unroll
                for (int ni = 0; ni < NI; ni++)
                    mma8(acc[mi][ni], af[mi], bf[ni]);
        }
    };

    issue(0, 0);
    const int NTILES = K / BK;
    for (int t = 0; t < NTILES; t++) {
        if (t + 1 < NTILES) { issue((t + 1) * BK, (t + 1) & 1); CP_WAIT(1); }
        else CP_WAIT(0);
        __syncthreads();
        compute(t & 1);
        __syncthreads();
    }

    #pragma unroll
    for (int mi = 0; mi < MI; mi++) {
        int row = m0 + mW + mi * 16 + r;
        #pragma unroll
        for (int ni = 0; ni < NI; ni++) {
            int col = n0 + nW + ni * 8 + 2 * cq;
            float2 v0 = make_float2(acc[mi][ni][0], acc[mi][ni][1]);
            float2 v1 = make_float2(acc[mi][ni][2], acc[mi][ni][3]);
            if constexpr (BIAS) {
                float b0 = bias[col], b1 = bias[col + 1];
                v0.x += b0; v0.y += b1; v1.x += b0; v1.y += b1;
            }
            *(float2*)(C + (long)row * N + col) = v0;
            *(float2*)(C + (long)(row + 8) * N + col) = v1;
        }
    }
}

// ---------------- b2[e] = dot(Wo[e,:], bv) + bo[e] ----------------
__global__ void __launch_bounds__(256) k_b2(const float* __restrict__ Wo,
                                            const float* __restrict__ bv,
                                            const float* __restrict__ bo) {
    int e = blockIdx.x * 256 + threadIdx.x;
    const float4* wo = (const float4*)(Wo + (long)e * HIDDEN);
    const float4* bvv = (const float4*)bv;
    float acc = 0.0f;
    #pragma unroll 4
    for (int i = 0; i < HIDDEN / 4; i++) {
        float4 a = wo[i], b = bvv[i];
        acc = fmaf(a.x, b.x, acc); acc = fmaf(a.y, b.y, acc);
        acc = fmaf(a.z, b.z, acc); acc = fmaf(a.w, b.w, acc);
    }
    g_b2[e] = acc + bo[e];
}

// ---------------- fused attention: 512 threads, Q2 in registers ----------------
#define LQ2 1032
#define OFF_X  0
#define OFF_SP (2 * TT * LQ2)                  // 16 warps x [16s x 16t]
#define OFF_P  (OFF_SP + 16 * 16 * TT)
#define OFF_M  (OFF_P + 16 * 24)
#define OFF_L  (OFF_M + 16)
#define OFF_SC (OFF_L + 16)
#define OFF_LG (OFF_SC + 16)
#define FUSED_SMEM ((OFF_LG + SEGLEN) * 4)

__global__ void __launch_bounds__(512) fused_attn(
    const float* __restrict__ X, const float* __restrict__ logits,
    float* __restrict__ Y)
{
    extern __shared__ float sm[];
    float* Xs  = sm + OFF_X;
    float* Sp  = sm + OFF_SP;
    float* Ps  = sm + OFF_P;
    float* mS  = sm + OFF_M;
    float* lS  = sm + OFF_L;
    float* scS = sm + OFF_SC;
    float* lgS = sm + OFF_LG;

    const int b    = blockIdx.x;
    const int tid  = threadIdx.x;
    const int lane = tid & 31;
    const int w    = tid >> 5;        // 0..15, d-chunk = [w*64, w*64+64)
    const int r    = lane >> 2;
    const int cq   = lane & 3;
    const float* Xb = X + (long)b * SEGLEN * HIDDEN;

    auto issueX = [&](int it) {
        int buf = it & 1;
        const float* src0 = Xb + (long)it * TT * HIDDEN;
        uint32_t dstb = smem_u32(Xs + buf * TT * LQ2);
        #pragma unroll
        for (int i = 0; i < 8; i++) {
            int idx = i * 512 + tid;          // 4096 float4 per stage
            int row = idx >> 8, c4 = idx & 255;
            cpasync16(dstb + (row * LQ2 + c4 * 4) * 4, src0 + row * HIDDEN + c4 * 4);
        }
        CP_COMMIT();
    };
    issueX(0);

    if (tid < 256) lgS[tid] = logits[(long)b * SEGLEN + tid];
    if (tid < 16) { mS[tid] = -INFINITY; lS[tid] = 0.0f; }

    // Q2 fragments in registers (Q2 already RNA-rounded to tf32-exact)
    uint32_t afq[8][4];
    #pragma unroll
    for (int k8 = 0; k8 < 8; k8++) {
        int col = w * 64 + k8 * 8 + cq;
        afq[k8][0] = f2u(__ldg(&g_q2[(long)r * HIDDEN + col]));
        afq[k8][1] = f2u(__ldg(&g_q2[(long)(r + 8) * HIDDEN + col]));
        afq[k8][2] = f2u(__ldg(&g_q2[(long)r * HIDDEN + col + 4]));
        afq[k8][3] = f2u(__ldg(&g_q2[(long)(r + 8) * HIDDEN + col + 4]));
    }

    float acc[8][4];
    #pragma unroll
    for (int ni = 0; ni < 8; ni++)
        #pragma unroll
        for (int j = 0; j < 4; j++) acc[ni][j] = 0.0f;

    __syncthreads();

    const int NT = SEGLEN / TT;   // 16 tiles
    for (int it = 0; it < NT; it++) {
        int buf = it & 1;
        if (it + 1 < NT) { issueX(it + 1); CP_WAIT(1); } else { CP_WAIT(0); }
        __syncthreads();
        const float* Xt = Xs + buf * TT * LQ2;

        // ---- scores: warp covers d in [w*64, w*64+64) ----
        {
            float sacc[2][4] = {{0,0,0,0},{0,0,0,0}};
            #pragma unroll
            for (int k8 = 0; k8 < 8; k8++) {
                int kk = w * 64 + k8 * 8;
                uint32_t bf[2][2];
                #pragma unroll
                for (int nt = 0; nt < 2; nt++) {
                    int nc = nt * 8 + r;
                    bf[nt][0] = f2u(Xt[nc * LQ2 + kk + cq]);
                    bf[nt][1] = f2u(Xt[nc * LQ2 + kk + cq + 4]);
                }
                mma8(sacc[0], afq[k8], bf[0]);
                mma8(sacc[1], afq[k8], bf[1]);
            }
            #pragma unroll
            for (int nt = 0; nt < 2; nt++) {
                int c0 = nt * 8 + 2 * cq;
                Sp[(w * 16 + r) * TT + c0]         = sacc[nt][0];
                Sp[(w * 16 + r) * TT + c0 + 1]     = sacc[nt][1];
                Sp[(w * 16 + r + 8) * TT + c0]     = sacc[nt][2];
                Sp[(w * 16 + r + 8) * TT + c0 + 1] = sacc[nt][3];
            }
        }
        __syncthreads();

        // ---- online softmax: thread (s = tid>>4, t = tid&15), tid < 256 ----
        if (tid < 256) {
            int s = tid >> 4, t = tid & 15;
            float accs = 0.0f;
            #pragma unroll
            for (int ww = 0; ww < 16; ww++) accs += Sp[(ww * 16 + s) * TT + t];
            float v = accs * SCALE + lgS[it * TT + t];
            float m_t = v;
            #pragma unroll
            for (int o = 8; o; o >>= 1) m_t = fmaxf(m_t, __shfl_xor_sync(0xffffffffu, m_t, o));
            float m_old = mS[s];
            float newm = fmaxf(m_old, m_t);
            float p = expf(v - newm);
            Ps[s * 24 + t] = tf32r(p);
            float sum = p;
            #pragma unroll
            for (int o = 8; o; o >>= 1) sum += __shfl_xor_sync(0xffffffffu, sum, o);
            if (t == 0) {
                float scale = expf(m_old - newm); // 0 on first tile
                lS[s] = lS[s] * scale + sum;
                mS[s] = newm;
                scS[s] = scale;
            }
        }
        __syncthreads();

        // ---- rescale Y acc, then Y += P @ X_tile ----
        {
            float sc0 = scS[r], sc1 = scS[r + 8];
            #pragma unroll
            for (int ni = 0; ni < 8; ni++) {
                acc[ni][0] *= sc0; acc[ni][1] *= sc0;
                acc[ni][2] *= sc1; acc[ni][3] *= sc1;
            }
            #pragma unroll
            for (int k8 = 0; k8 < 2; k8++) {
                uint32_t af[4];
                af[0] = f2u(Ps[r * 24 + k8 * 8 + cq]);
                af[1] = f2u(Ps[(r + 8) * 24 + k8 * 8 + cq]);
                af[2] = f2u(Ps[r * 24 + k8 * 8 + cq + 4]);
                af[3] = f2u(Ps[(r + 8) * 24 + k8 * 8 + cq + 4]);
                #pragma unroll
                for (int ni = 0; ni < 8; ni++) {
                    int nc = w * 64 + ni * 8 + r;
                    uint32_t bf[2];
                    bf[0] = f2u(Xt[(k8 * 8 + cq) * LQ2 + nc]);
                    bf[1] = f2u(Xt[(k8 * 8 + cq + 4) * LQ2 + nc]);
                    mma8(acc[ni], af, bf);
                }
            }
        }
        __syncthreads();   // protect Xs buffer + Ps/scS/mS/lS before next tile
    }

    // ---- epilogue: Y[b][s][d] = acc / l, RNA-rounded (tf32-exact for next GEMM) ----
    float inv0 = 1.0f / lS[r];
    float inv1 = 1.0f / lS[r + 8];
    float* Y0 = Y + ((long)b * SLOTS + r) * HIDDEN;
    float* Y1 = Y + ((long)b * SLOTS + r + 8) * HIDDEN;
    #pragma unroll
    for (int ni = 0; ni < 8; ni++) {
        int col = w * 64 + ni * 8 + 2 * cq;
        float2 v0 = make_float2(tf32r(acc[ni][0] * inv0), tf32r(acc[ni][1] * inv0));
        float2 v1 = make_float2(tf32r(acc[ni][2] * inv1), tf32r(acc[ni][3] * inv1));
        *(float2*)(Y0 + col) = v0;
        *(float2*)(Y1 + col) = v1;
    }
}

// ---------------- launch ----------------
extern "C" void kernel_launch(void* const* d_in, const int* in_sizes, int n_in,
                              void* d_out, int out_size) {
    const float* X      = (const float*)d_in[0];   // [512,256,1024]
    const float* logits = (const float*)d_in[1];   // [512,256]
    const float* LQ     = (const float*)d_in[2];   // [16,1024]
    const float* Wq     = (const float*)d_in[3];
    const float* bq     = (const float*)d_in[4];
    const float* Wk     = (const float*)d_in[5];
    // d_in[6] = bk: cancels in softmax, unused
    const float* Wv     = (const float*)d_in[7];
    const float* bv     = (const float*)d_in[8];
    const float* Wo     = (const float*)d_in[9];
    const float* bo     = (const float*)d_in[10];
    float* out = (float*)d_out;

    float *q1p, *q2p, *w2p, *b2p, *yp;
    cudaGetSymbolAddress((void**)&q1p, g_q1);
    cudaGetSymbolAddress((void**)&q2p, g_q2);
    cudaGetSymbolAddress((void**)&w2p, g_w2);
    cudaGetSymbolAddress((void**)&b2p, g_b2);
    cudaGetSymbolAddress((void**)&yp,  g_y);

    cudaFuncSetAttribute((const void*)gemm_cpa<128,128,32,2,4,true>,
                         cudaFuncAttributeMaxDynamicSharedMemorySize, 81920);
    cudaFuncSetAttribute((const void*)fused_attn,
                         cudaFuncAttributeMaxDynamicSharedMemorySize, FUSED_SMEM);

    // 1) q1 = LQ @ Wq^T + bq    [16,1024]
    gemm_p<16, 64, 32, 1, 4, true, true, true><<<dim3(16, 1), 128, 25600>>>(
        LQ, Wq, q1p, bq, 16, 1024, 1024);
    // 2) Q2 = q1 @ Wk           [16,1024]
    gemm_p<16, 64, 32, 1, 4, false, false, true><<<dim3(16, 1), 128, 23552>>>(
        q1p, Wk, q2p, nullptr, 16, 1024, 1024);
    // 3) b2 = Wo @ bv + bo
    k_b2<<<4, 256>>>(Wo, bv, bo);
    // 4) W2 = Wo @ Wv           [1024,1024]  (raw fp32 inputs -> convert path)
    gemm_p<64, 64, 32, 2, 2, false, false, true><<<dim3(16, 16), 128, 38912>>>(
        Wo, Wv, w2p, nullptr, 1024, 1024, 1024);
    // 5) fused attention: Y[b] = softmax(Q2·X^T/32 + logits) @ X   (X read once)
    fused_attn<<<BSZ, 512, FUSED_SMEM>>>(X, logits, yp);
    // 6) out = Y @ W2^T + b2    [8192,1024]  (inputs tf32-exact -> cp.async path)
    gemm_cpa<128, 128, 32, 2, 4, true><<<dim3(8, 64), 256, 81920>>>(
        yp, w2p, out, b2p, BSZ * SLOTS, HIDDEN, HIDDEN);
}

// round 6
// speedup vs baseline: 2.0590x; 1.1793x over previous
#include <cuda_runtime.h>
#include <cstdint>

#define HIDDEN 1024
#define SLOTS 16
#define BSZ 512
#define SEGLEN 256
#define TT 16            // t-tile in fused attention
#define SCALE 0.03125f   // 1/sqrt(1024)

// ---------------- scratch (device globals; no allocation) ----------------
__device__ float g_q1[SLOTS * HIDDEN];
__device__ float g_q2[SLOTS * HIDDEN];
__device__ float g_w2[HIDDEN * HIDDEN];
__device__ float g_b2[HIDDEN];
__device__ float g_y[(size_t)BSZ * SLOTS * HIDDEN];      // [b][s][d]

// ---------------- helpers ----------------
__device__ __forceinline__ float tf32r(float x) {
    uint32_t u;
    asm("cvt.rna.tf32.f32 %0, %1;" : "=r"(u) : "f"(x));
    return __uint_as_float(u);
}
__device__ __forceinline__ uint32_t f2u(float x) { return __float_as_uint(x); }

__device__ __forceinline__ void mma8(float* c, const uint32_t* a, const uint32_t* b) {
    asm volatile(
        "mma.sync.aligned.m16n8k8.row.col.f32.tf32.tf32.f32 "
        "{%0,%1,%2,%3},{%4,%5,%6,%7},{%8,%9},{%0,%1,%2,%3};"
        : "+f"(c[0]), "+f"(c[1]), "+f"(c[2]), "+f"(c[3])
        : "r"(a[0]), "r"(a[1]), "r"(a[2]), "r"(a[3]), "r"(b[0]), "r"(b[1]));
}

__device__ __forceinline__ uint32_t smem_u32(const void* p) {
    uint32_t a;
    asm("{ .reg .u64 t; cvta.to.shared.u64 t, %1; cvt.u32.u64 %0, t; }" : "=r"(a) : "l"(p));
    return a;
}
__device__ __forceinline__ void cpasync16(uint32_t dst, const void* src) {
    asm volatile("cp.async.cg.shared.global [%0], [%1], 16;" :: "r"(dst), "l"(src));
}
#define CP_COMMIT() asm volatile("cp.async.commit_group;")
#define CP_WAIT(n)  asm volatile("cp.async.wait_group %0;" :: "n"(n))

// ---------------- multi-stage cp.async tf32 GEMM ----------------
// C[m,n] = sum_k A[m,k] * (BT ? B[n,k] : B[k,n])  (+ bias[n] if BIAS)
// fp32 loaded raw; mma hardware truncates to tf32 (RZ). Epilogue optional RNA.
template <int BM, int BN, int BK, int WM, int WN, int STAGES,
          bool BT, bool BIAS, bool RNA, int MINCTA>
__global__ void __launch_bounds__(WM * WN * 32, MINCTA) gemm_cpa(
    const float* __restrict__ A, const float* __restrict__ B,
    float* __restrict__ C, const float* __restrict__ bias,
    int M, int N, int K)
{
    constexpr int THREADS = WM * WN * 32;
    constexpr int LA = BK + 8;
    constexpr int LB = BN + 8;
    constexpr int ASZ = BM * LA;
    constexpr int BSZE = BT ? BN * LA : BK * LB;
    constexpr int AITER = BM * BK / 4 / THREADS;
    constexpr int BITER = BN * BK / 4 / THREADS;

    extern __shared__ float sm[];

    const int tid  = threadIdx.x;
    const int lane = tid & 31;
    const int warp = tid >> 5;
    const int r  = lane >> 2;
    const int cq = lane & 3;
    const int wm = warp / WN, wn = warp % WN;
    constexpr int WTM = BM / WM, WTN = BN / WN;
    constexpr int MI = WTM / 16, NI = WTN / 8;
    const int mW = wm * WTM, nW = wn * WTN;
    const int m0 = blockIdx.y * BM;
    const int n0 = blockIdx.x * BN;

    float acc[MI][NI][4];
    #pragma unroll
    for (int mi = 0; mi < MI; mi++)
        #pragma unroll
        for (int ni = 0; ni < NI; ni++)
            #pragma unroll
            for (int j = 0; j < 4; j++) acc[mi][ni][j] = 0.0f;

    auto issue = [&](int k0, int buf) {
        float* As = sm + buf * (ASZ + BSZE);
        float* Bs = As + ASZ;
        uint32_t ab = smem_u32(As);
        uint32_t bb = smem_u32(Bs);
        #pragma unroll
        for (int i = 0; i < AITER; i++) {
            int idx = i * THREADS + tid;
            int row = idx / (BK / 4), k4 = idx % (BK / 4);
            cpasync16(ab + (row * LA + k4 * 4) * 4,
                      A + (long)(m0 + row) * K + k0 + k4 * 4);
        }
        if constexpr (BT) {
            #pragma unroll
            for (int i = 0; i < BITER; i++) {
                int idx = i * THREADS + tid;
                int row = idx / (BK / 4), k4 = idx % (BK / 4);
                cpasync16(bb + (row * LA + k4 * 4) * 4,
                          B + (long)(n0 + row) * K + k0 + k4 * 4);
            }
        } else {
            #pragma unroll
            for (int i = 0; i < BITER; i++) {
                int idx = i * THREADS + tid;
                int row = idx / (BN / 4), n4 = idx % (BN / 4);
                cpasync16(bb + (row * LB + n4 * 4) * 4,
                          B + (long)(k0 + row) * N + n0 + n4 * 4);
            }
        }
        CP_COMMIT();
    };
    auto compute = [&](int buf) {
        const float* As = sm + buf * (ASZ + BSZE);
        const float* Bs = As + ASZ;
        #pragma unroll
        for (int k8 = 0; k8 < BK / 8; k8++) {
            uint32_t af[MI][4], bf[NI][2];
            #pragma unroll
            for (int mi = 0; mi < MI; mi++) {
                int mr = mW + mi * 16 + r;
                af[mi][0] = f2u(As[mr * LA + k8 * 8 + cq]);
                af[mi][1] = f2u(As[(mr + 8) * LA + k8 * 8 + cq]);
                af[mi][2] = f2u(As[mr * LA + k8 * 8 + cq + 4]);
                af[mi][3] = f2u(As[(mr + 8) * LA + k8 * 8 + cq + 4]);
            }
            #pragma unroll
            for (int ni = 0; ni < NI; ni++) {
                int nc = nW + ni * 8 + r;
                if constexpr (BT) {
                    bf[ni][0] = f2u(Bs[nc * LA + k8 * 8 + cq]);
                    bf[ni][1] = f2u(Bs[nc * LA + k8 * 8 + cq + 4]);
                } else {
                    bf[ni][0] = f2u(Bs[(k8 * 8 + cq) * LB + nc]);
                    bf[ni][1] = f2u(Bs[(k8 * 8 + cq + 4) * LB + nc]);
                }
            }
            #pragma unroll
            for (int mi = 0; mi < MI; mi++)
                #pragma unroll
                for (int ni = 0; ni < NI; ni++)
                    mma8(acc[mi][ni], af[mi], bf[ni]);
        }
    };

    const int NTILES = K / BK;
    #pragma unroll
    for (int s = 0; s < STAGES - 1; s++) issue(s * BK, s);

    for (int t = 0; t < NTILES; t++) {
        if (t + STAGES - 1 < NTILES) {
            issue((t + STAGES - 1) * BK, (t + STAGES - 1) % STAGES);
            CP_WAIT(STAGES - 1);
        } else {
            int rem = NTILES - 1 - t;   // ≤ STAGES-2
            if constexpr (STAGES >= 4) { if (rem == 2) CP_WAIT(2); }
            if (rem == 1) CP_WAIT(1);
            else if (rem == 0) CP_WAIT(0);
        }
        __syncthreads();
        compute(t % STAGES);
        __syncthreads();
    }

    #pragma unroll
    for (int mi = 0; mi < MI; mi++) {
        int row = m0 + mW + mi * 16 + r;
        #pragma unroll
        for (int ni = 0; ni < NI; ni++) {
            int col = n0 + nW + ni * 8 + 2 * cq;
            float2 v0 = make_float2(acc[mi][ni][0], acc[mi][ni][1]);
            float2 v1 = make_float2(acc[mi][ni][2], acc[mi][ni][3]);
            if constexpr (BIAS) {
                float b0 = bias[col], b1 = bias[col + 1];
                v0.x += b0; v0.y += b1; v1.x += b0; v1.y += b1;
            }
            if constexpr (RNA) {
                v0.x = tf32r(v0.x); v0.y = tf32r(v0.y);
                v1.x = tf32r(v1.x); v1.y = tf32r(v1.y);
            }
            *(float2*)(C + (long)row * N + col) = v0;
            *(float2*)(C + (long)(row + 8) * N + col) = v1;
        }
    }
}

// ---------------- b2[e] = dot(Wo[e,:], bv) + bo[e] ----------------
__global__ void __launch_bounds__(256) k_b2(const float* __restrict__ Wo,
                                            const float* __restrict__ bv,
                                            const float* __restrict__ bo) {
    int e = blockIdx.x * 256 + threadIdx.x;
    const float4* wo = (const float4*)(Wo + (long)e * HIDDEN);
    const float4* bvv = (const float4*)bv;
    float acc = 0.0f;
    #pragma unroll 4
    for (int i = 0; i < HIDDEN / 4; i++) {
        float4 a = wo[i], b = bvv[i];
        acc = fmaf(a.x, b.x, acc); acc = fmaf(a.y, b.y, acc);
        acc = fmaf(a.z, b.z, acc); acc = fmaf(a.w, b.w, acc);
    }
    g_b2[e] = acc + bo[e];
}

// ---------------- fused attention: 512 threads, 3-stage cp.async, Q2 in regs ----------------
#define LQ2 1032
#define OFF_X  0
#define OFF_SP (3 * TT * LQ2)
#define OFF_P  (OFF_SP + 16 * 16 * TT)
#define OFF_M  (OFF_P + 16 * 24)
#define OFF_L  (OFF_M + 16)
#define OFF_SC (OFF_L + 16)
#define OFF_LG (OFF_SC + 16)
#define FUSED_SMEM ((OFF_LG + SEGLEN) * 4)

__global__ void __launch_bounds__(512, 1) fused_attn(
    const float* __restrict__ X, const float* __restrict__ logits,
    float* __restrict__ Y)
{
    extern __shared__ float sm[];
    float* Xs  = sm + OFF_X;
    float* Sp  = sm + OFF_SP;
    float* Ps  = sm + OFF_P;
    float* mS  = sm + OFF_M;
    float* lS  = sm + OFF_L;
    float* scS = sm + OFF_SC;
    float* lgS = sm + OFF_LG;

    const int b    = blockIdx.x;
    const int tid  = threadIdx.x;
    const int lane = tid & 31;
    const int w    = tid >> 5;        // 0..15, d-chunk = [w*64, w*64+64)
    const int r    = lane >> 2;
    const int cq   = lane & 3;
    const float* Xb = X + (long)b * SEGLEN * HIDDEN;

    auto issueX = [&](int it) {
        int buf = it % 3;
        const float* src0 = Xb + (long)it * TT * HIDDEN;
        uint32_t dstb = smem_u32(Xs + buf * TT * LQ2);
        #pragma unroll
        for (int i = 0; i < 8; i++) {
            int idx = i * 512 + tid;          // 4096 float4 per stage
            int row = idx >> 8, c4 = idx & 255;
            cpasync16(dstb + (row * LQ2 + c4 * 4) * 4, src0 + row * HIDDEN + c4 * 4);
        }
        CP_COMMIT();
    };
    issueX(0); issueX(1);

    if (tid < 256) lgS[tid] = logits[(long)b * SEGLEN + tid];
    if (tid < 16) { mS[tid] = -INFINITY; lS[tid] = 0.0f; }

    // Q2 fragments in registers (Q2 is RNA-rounded tf32-exact)
    uint32_t afq[8][4];
    #pragma unroll
    for (int k8 = 0; k8 < 8; k8++) {
        int col = w * 64 + k8 * 8 + cq;
        afq[k8][0] = f2u(__ldg(&g_q2[(long)r * HIDDEN + col]));
        afq[k8][1] = f2u(__ldg(&g_q2[(long)(r + 8) * HIDDEN + col]));
        afq[k8][2] = f2u(__ldg(&g_q2[(long)r * HIDDEN + col + 4]));
        afq[k8][3] = f2u(__ldg(&g_q2[(long)(r + 8) * HIDDEN + col + 4]));
    }

    float acc[8][4];
    #pragma unroll
    for (int ni = 0; ni < 8; ni++)
        #pragma unroll
        for (int j = 0; j < 4; j++) acc[ni][j] = 0.0f;

    __syncthreads();

    const int NT = SEGLEN / TT;   // 16 tiles
    for (int it = 0; it < NT; it++) {
        if (it + 2 < NT) { issueX(it + 2); CP_WAIT(2); }
        else if (NT - 1 - it == 1) CP_WAIT(1);
        else CP_WAIT(0);
        __syncthreads();
        const float* Xt = Xs + (it % 3) * TT * LQ2;

        // ---- scores: warp covers d in [w*64, w*64+64) ----
        {
            float sacc[2][4] = {{0,0,0,0},{0,0,0,0}};
            #pragma unroll
            for (int k8 = 0; k8 < 8; k8++) {
                int kk = w * 64 + k8 * 8;
                uint32_t bf[2][2];
                #pragma unroll
                for (int nt = 0; nt < 2; nt++) {
                    int nc = nt * 8 + r;
                    bf[nt][0] = f2u(Xt[nc * LQ2 + kk + cq]);
                    bf[nt][1] = f2u(Xt[nc * LQ2 + kk + cq + 4]);
                }
                mma8(sacc[0], afq[k8], bf[0]);
                mma8(sacc[1], afq[k8], bf[1]);
            }
            #pragma unroll
            for (int nt = 0; nt < 2; nt++) {
                int c0 = nt * 8 + 2 * cq;
                Sp[(w * 16 + r) * TT + c0]         = sacc[nt][0];
                Sp[(w * 16 + r) * TT + c0 + 1]     = sacc[nt][1];
                Sp[(w * 16 + r + 8) * TT + c0]     = sacc[nt][2];
                Sp[(w * 16 + r + 8) * TT + c0 + 1] = sacc[nt][3];
            }
        }
        __syncthreads();

        // ---- online softmax: thread (s = tid>>4, t = tid&15), tid < 256 ----
        if (tid < 256) {
            int s = tid >> 4, t = tid & 15;
            float accs = 0.0f;
            #pragma unroll
            for (int ww = 0; ww < 16; ww++) accs += Sp[(ww * 16 + s) * TT + t];
            float v = accs * SCALE + lgS[it * TT + t];
            float m_t = v;
            #pragma unroll
            for (int o = 8; o; o >>= 1) m_t = fmaxf(m_t, __shfl_xor_sync(0xffffffffu, m_t, o));
            float m_old = mS[s];
            float newm = fmaxf(m_old, m_t);
            float p = expf(v - newm);
            Ps[s * 24 + t] = tf32r(p);
            float sum = p;
            #pragma unroll
            for (int o = 8; o; o >>= 1) sum += __shfl_xor_sync(0xffffffffu, sum, o);
            if (t == 0) {
                float scale = expf(m_old - newm); // 0 on first tile
                lS[s] = lS[s] * scale + sum;
                mS[s] = newm;
                scS[s] = scale;
            }
        }
        __syncthreads();

        // ---- rescale Y acc, then Y += P @ X_tile ----
        {
            float sc0 = scS[r], sc1 = scS[r + 8];
            #pragma unroll
            for (int ni = 0; ni < 8; ni++) {
                acc[ni][0] *= sc0; acc[ni][1] *= sc0;
                acc[ni][2] *= sc1; acc[ni][3] *= sc1;
            }
            #pragma unroll
            for (int k8 = 0; k8 < 2; k8++) {
                uint32_t af[4];
                af[0] = f2u(Ps[r * 24 + k8 * 8 + cq]);
                af[1] = f2u(Ps[(r + 8) * 24 + k8 * 8 + cq]);
                af[2] = f2u(Ps[r * 24 + k8 * 8 + cq + 4]);
                af[3] = f2u(Ps[(r + 8) * 24 + k8 * 8 + cq + 4]);
                #pragma unroll
                for (int ni = 0; ni < 8; ni++) {
                    int nc = w * 64 + ni * 8 + r;
                    uint32_t bf[2];
                    bf[0] = f2u(Xt[(k8 * 8 + cq) * LQ2 + nc]);
                    bf[1] = f2u(Xt[(k8 * 8 + cq + 4) * LQ2 + nc]);
                    mma8(acc[ni], af, bf);
                }
            }
        }
        __syncthreads();   // protect Xs buffer + Ps/scS/mS/lS before next tile
    }

    // ---- epilogue: Y[b][s][d] = acc / l, RNA-rounded (tf32-exact for next GEMM) ----
    float inv0 = 1.0f / lS[r];
    float inv1 = 1.0f / lS[r + 8];
    float* Y0 = Y + ((long)b * SLOTS + r) * HIDDEN;
    float* Y1 = Y + ((long)b * SLOTS + r + 8) * HIDDEN;
    #pragma unroll
    for (int ni = 0; ni < 8; ni++) {
        int col = w * 64 + ni * 8 + 2 * cq;
        float2 v0 = make_float2(tf32r(acc[ni][0] * inv0), tf32r(acc[ni][1] * inv0));
        float2 v1 = make_float2(tf32r(acc[ni][2] * inv1), tf32r(acc[ni][3] * inv1));
        *(float2*)(Y0 + col) = v0;
        *(float2*)(Y1 + col) = v1;
    }
}

// ---------------- launch ----------------
extern "C" void kernel_launch(void* const* d_in, const int* in_sizes, int n_in,
                              void* d_out, int out_size) {
    const float* X      = (const float*)d_in[0];   // [512,256,1024]
    const float* logits = (const float*)d_in[1];   // [512,256]
    const float* LQ     = (const float*)d_in[2];   // [16,1024]
    const float* Wq     = (const float*)d_in[3];
    const float* bq     = (const float*)d_in[4];
    const float* Wk     = (const float*)d_in[5];
    // d_in[6] = bk: cancels in softmax, unused
    const float* Wv     = (const float*)d_in[7];
    const float* bv     = (const float*)d_in[8];
    const float* Wo     = (const float*)d_in[9];
    const float* bo     = (const float*)d_in[10];
    float* out = (float*)d_out;

    float *q1p, *q2p, *w2p, *b2p, *yp;
    cudaGetSymbolAddress((void**)&q1p, g_q1);
    cudaGetSymbolAddress((void**)&q2p, g_q2);
    cudaGetSymbolAddress((void**)&w2p, g_w2);
    cudaGetSymbolAddress((void**)&b2p, g_b2);
    cudaGetSymbolAddress((void**)&yp,  g_y);

    // smem opt-in (idempotent)
    cudaFuncSetAttribute((const void*)gemm_cpa<16,64,32,1,4,4,true,true,true,1>,
                         cudaFuncAttributeMaxDynamicSharedMemorySize, 51200);
    cudaFuncSetAttribute((const void*)gemm_cpa<16,64,32,1,4,4,false,false,true,1>,
                         cudaFuncAttributeMaxDynamicSharedMemorySize, 47104);
    cudaFuncSetAttribute((const void*)gemm_cpa<64,64,32,2,2,3,false,false,true,1>,
                         cudaFuncAttributeMaxDynamicSharedMemorySize, 58368);
    cudaFuncSetAttribute((const void*)gemm_cpa<128,128,32,4,2,2,true,true,false,2>,
                         cudaFuncAttributeMaxDynamicSharedMemorySize, 81920);
    cudaFuncSetAttribute((const void*)fused_attn,
                         cudaFuncAttributeMaxDynamicSharedMemorySize, FUSED_SMEM);

    // 1) q1 = LQ @ Wq^T + bq    [16,1024]
    gemm_cpa<16, 64, 32, 1, 4, 4, true, true, true, 1><<<dim3(16, 1), 128, 51200>>>(
        LQ, Wq, q1p, bq, 16, 1024, 1024);
    // 2) Q2 = q1 @ Wk           [16,1024]
    gemm_cpa<16, 64, 32, 1, 4, 4, false, false, true, 1><<<dim3(16, 1), 128, 47104>>>(
        q1p, Wk, q2p, nullptr, 16, 1024, 1024);
    // 3) b2 = Wo @ bv + bo
    k_b2<<<4, 256>>>(Wo, bv, bo);
    // 4) W2 = Wo @ Wv           [1024,1024]
    gemm_cpa<64, 64, 32, 2, 2, 3, false, false, true, 1><<<dim3(16, 16), 128, 58368>>>(
        Wo, Wv, w2p, nullptr, 1024, 1024, 1024);
    // 5) fused attention: Y[b] = softmax(Q2·X^T/32 + logits) @ X   (X read once)
    fused_attn<<<BSZ, 512, FUSED_SMEM>>>(X, logits, yp);
    // 6) out = Y @ W2^T + b2    [8192,1024]
    gemm_cpa<128, 128, 32, 4, 2, 2, true, true, false, 2><<<dim3(8, 64), 256, 81920>>>(
        yp, w2p, out, b2p, BSZ * SLOTS, HIDDEN, HIDDEN);
}